// round 16
// baseline (speedup 1.0000x reference)
#include <cuda_runtime.h>

typedef unsigned long long ull;

#define N_NODES 2048
#define NODE_DIM 128
#define HIDDEN 64

// Scratch (no allocation allowed — device globals; zero-initialized at load,
// pad slots are never written so they stay zero across all replays)
// Channel-permuted, pre-scaled staging: slots 0..P-1 = positive c (pad to even),
// then negatives (pad to even). Value scaled by |c_h|/2.
// Layout: float[(slot>>1)][node][slot&1] -> ull pairs [pair][node].
__device__ __align__(16) float g_AT[34 * N_NODES * 2];
__device__ __align__(16) float g_BT[34 * N_NODES * 2];
__device__ __align__(16) float g_Sa[N_NODES];            // b2 + sum_h (c/2) a_ih
__device__ __align__(16) float g_Sb[N_NODES];            // sum_h (c/2) b_jh
__device__ int g_PP;     // # positive pairs (ceil(P/2))
__device__ int g_NP;     // # negative pairs (ceil((64-P)/2))

// ---------------------------------------------------------------------------
// Fused prep: per block of 16 nodes:
//   phase A: H = X @ W_enc + b_enc           (into smem Hs)
//   phase B: [a|b] = H @ [Wa|Wb] (+b1 on a), scale each channel by |c_h|/2,
//            scatter-store into sign-permuted slots of g_AT/g_BT;
//            Sa/Sb separable sums via smem reduce.
// Slot permutation computed in-kernel via ballot masks (no setup kernel).
// ---------------------------------------------------------------------------
__global__ __launch_bounds__(256, 2) void prep(const float* __restrict__ X,
                                               const float* __restrict__ W_enc,
                                               const float* __restrict__ b_enc,
                                               const float* __restrict__ W1,
                                               const float* __restrict__ b1,
                                               const float* __restrict__ W2,
                                               const float* __restrict__ b2)
{
    __shared__ union {
        struct {
            float Xs[16][129];          // stride 129 -> conflict-free
            ull   We[NODE_DIM][32];     // W_enc col-pairs
        } A;
        ull W1s[128][32];               // phase B: full W1 as col-pairs
    } u;
    __shared__ float Hs[16][65];        // H tile, stride 65
    __shared__ ull   bes[32];           // b_enc pairs
    __shared__ ull   b1s[32];           // b1 pairs
    __shared__ float c2s[64];           // c/2 (signed)
    __shared__ float cab[64];           // |c|/2 per channel
    __shared__ int   sml[64];           // slot of h
    __shared__ unsigned smask[2];       // sign ballots (h 0..31, 32..63)
    __shared__ float pa[16][17], pb[16][17];

    const int t  = threadIdx.x;
    const int n0 = blockIdx.x * 16;
    const int tx = t & 15;              // node lane
    const int ty = t >> 4;              // 0..15

    // ---- phase A fills ----
    for (int idx = t; idx < NODE_DIM * 32; idx += 256) {
        int k = idx >> 5, p = idx & 31;
        u.A.We[k][p] = *(const ull*)&W_enc[k * HIDDEN + 2 * p];
    }
    for (int idx = t; idx < 16 * NODE_DIM; idx += 256) {
        int n = idx >> 7, d = idx & 127;
        u.A.Xs[n][d] = X[(n0 + n) * NODE_DIM + d];
    }
    if (t < 32) bes[t] = *(const ull*)&b_enc[2 * t];
    else if (t >= 64 && t < 96) b1s[t - 64] = *(const ull*)&b1[2 * (t - 64)];
    if (t >= 128 && t < 192) {
        int h = t - 128;
        float w = W2[h];
        c2s[h] = 0.5f * w;
        cab[h] = 0.5f * fabsf(w);
        unsigned m = __ballot_sync(0xffffffffu, w >= 0.0f);
        if ((t & 31) == 0) smask[(t >> 5) & 1] = m;
    }
    __syncthreads();

    // ---- slot permutation (between syncs; consumed after next sync) ----
    if (t >= 128 && t < 192) {
        int h = t - 128;
        unsigned mA = smask[0], mB = smask[1];
        int P  = __popc(mA) + __popc(mB);
        int PP = (P + 1) >> 1;
        unsigned lowmask = (1u << (h & 31)) - 1u;
        bool pos;
        int posBefore;
        if (h < 32) {
            pos = (mA >> h) & 1u;
            posBefore = __popc(mA & lowmask);
        } else {
            pos = (mB >> (h - 32)) & 1u;
            posBefore = __popc(mA) + __popc(mB & lowmask);
        }
        sml[h] = pos ? posBefore : 2 * PP + (h - posBefore);
        if (t == 128) {
            g_PP = PP;
            g_NP = (64 - P + 1) >> 1;
        }
    }

    // ---- phase A compute: thread (tx, p0=ty) does pairs p0, p0+16 ----
    {
        ull acc0 = 0ull, acc1 = 0ull;
        #pragma unroll 8
        for (int k = 0; k < NODE_DIM; k++) {
            unsigned xu = __float_as_uint(u.A.Xs[tx][k]);
            ull x2;
            asm("mov.b64 %0, {%1, %2};" : "=l"(x2) : "r"(xu), "r"(xu));
            ull w0 = u.A.We[k][ty];
            ull w1 = u.A.We[k][ty + 16];
            asm("fma.rn.f32x2 %0, %1, %2, %0;" : "+l"(acc0) : "l"(x2), "l"(w0));
            asm("fma.rn.f32x2 %0, %1, %2, %0;" : "+l"(acc1) : "l"(x2), "l"(w1));
        }
        #pragma unroll
        for (int v = 0; v < 2; v++) {
            const int p = ty + 16 * v;
            ull a = v ? acc1 : acc0;
            asm("add.rn.f32x2 %0, %0, %1;" : "+l"(a) : "l"(bes[p]));
            unsigned lo_u, hi_u;
            asm("mov.b64 {%0, %1}, %2;" : "=r"(lo_u), "=r"(hi_u) : "l"(a));
            Hs[tx][2 * p]     = __uint_as_float(lo_u);
            Hs[tx][2 * p + 1] = __uint_as_float(hi_u);
        }
    }
    __syncthreads();     // Hs + sml complete; phase A buffers now dead

    // ---- phase B fill: W1 over the union ----
    for (int idx = t; idx < 128 * 32; idx += 256) {
        int k = idx >> 5, p = idx & 31;
        u.W1s[k][p] = *(const ull*)&W1[k * HIDDEN + 2 * p];
    }
    __syncthreads();

    // ---- phase B compute: thread (tx, ty) does 4 pair-chains ----
    ull acc[4];
    #pragma unroll
    for (int v = 0; v < 4; v++) acc[v] = 0ull;

    #pragma unroll 8
    for (int k = 0; k < HIDDEN; k++) {
        unsigned xu = __float_as_uint(Hs[tx][k]);
        ull x2;
        asm("mov.b64 %0, {%1, %2};" : "=l"(x2) : "r"(xu), "r"(xu));
        ull wa0 = u.W1s[k][ty];
        ull wa1 = u.W1s[k][ty + 16];
        ull wb0 = u.W1s[64 + k][ty];
        ull wb1 = u.W1s[64 + k][ty + 16];
        asm("fma.rn.f32x2 %0, %1, %2, %0;" : "+l"(acc[0]) : "l"(x2), "l"(wa0));
        asm("fma.rn.f32x2 %0, %1, %2, %0;" : "+l"(acc[1]) : "l"(x2), "l"(wa1));
        asm("fma.rn.f32x2 %0, %1, %2, %0;" : "+l"(acc[2]) : "l"(x2), "l"(wb0));
        asm("fma.rn.f32x2 %0, %1, %2, %0;" : "+l"(acc[3]) : "l"(x2), "l"(wb1));
    }

    float pA = 0.f, pB = 0.f;
    const int node = n0 + tx;
    #pragma unroll
    for (int v = 0; v < 4; v++) {
        const int pl = (v & 1) ? ty + 16 : ty;       // pair index within half
        const int h0 = 2 * pl, h1 = 2 * pl + 1;      // original channels
        ull w = acc[v];
        if (v < 2)
            asm("add.rn.f32x2 %0, %0, %1;" : "+l"(w) : "l"(b1s[pl]));
        unsigned lo_u, hi_u;
        asm("mov.b64 {%0, %1}, %2;" : "=r"(lo_u), "=r"(hi_u) : "l"(w));
        float vx = __uint_as_float(lo_u), vy = __uint_as_float(hi_u);
        // separable sum uses signed c/2 with UNSCALED values
        float contrib = vx * c2s[h0] + vy * c2s[h1];
        if (v < 2) pA += contrib; else pB += contrib;
        // scatter-store pre-scaled by |c|/2 into sign-permuted slots
        float* dst = (v < 2) ? g_AT : g_BT;
        const int s0 = sml[h0], s1 = sml[h1];
        dst[((s0 >> 1) * N_NODES + node) * 2 + (s0 & 1)] = vx * cab[h0];
        dst[((s1 >> 1) * N_NODES + node) * 2 + (s1 & 1)] = vy * cab[h1];
    }
    pa[ty][tx] = pA;
    pb[ty][tx] = pB;
    __syncthreads();

    if (t < 16) {
        float s = __ldg(b2);
        #pragma unroll
        for (int q = 0; q < 16; q++) s += pa[q][t];
        g_Sa[n0 + t] = s;
    } else if (t < 32) {
        float s = 0.f;
        #pragma unroll
        for (int q = 0; q < 16; q++) s += pb[q][t - 16];
        g_Sb[n0 + t - 16] = s;
    }
}

// ---------------------------------------------------------------------------
// Pairwise inner step. MODE 0: both c>=0 (acc += |s|, and.b64 imm).
// MODE 1: both c<0 (acc += -|s|, or.b64 imm). Pad slots are zero -> no-ops.
// 4x8 micro-tile: 12 LDS.64 feed 32 pair-chains (crossbar 69% vs 89% at 4x4).
// ---------------------------------------------------------------------------
template<int MODE>
__device__ __forceinline__ void do_hh(const ull* __restrict__ Arow,
                                      const ull* __restrict__ Brow,
                                      int ty, int tx, ull (&acc)[4][8])
{
    ull av[4], bv[8];
    #pragma unroll
    for (int r = 0; r < 4; r++) av[r] = Arow[ty + 16 * r];
    #pragma unroll
    for (int c = 0; c < 8; c++) bv[c] = Brow[tx + 8 * c];
    #pragma unroll
    for (int r = 0; r < 4; r++) {
        #pragma unroll
        for (int c = 0; c < 8; c++) {
            if (MODE == 0) {
                asm("{\n\t.reg .b64 s;\n\t"
                    "add.rn.f32x2 s, %1, %2;\n\t"
                    "and.b64 s, s, 0x7FFFFFFF7FFFFFFF;\n\t"
                    "add.rn.f32x2 %0, %0, s;\n\t}"
                    : "+l"(acc[r][c]) : "l"(av[r]), "l"(bv[c]));
            } else {
                asm("{\n\t.reg .b64 s;\n\t"
                    "add.rn.f32x2 s, %1, %2;\n\t"
                    "or.b64 s, s, 0x8000000080000000;\n\t"
                    "add.rn.f32x2 %0, %0, s;\n\t}"
                    : "+l"(acc[r][c]) : "l"(av[r]), "l"(bv[c]));
            }
        }
    }
}

// ---------------------------------------------------------------------------
// Main: logit_ij = Sa_i + Sb_j + sum_pos |s'| - sum_neg |s'|, out=sigmoid, diag=0
// 64x64 tile, 128 threads, 4x8 micro-tile, smem [pair][node] stride 65.
// ---------------------------------------------------------------------------
__global__ __launch_bounds__(128, 4) void pairwise(float* __restrict__ out)
{
    __shared__ ull  As[33 * 65];     // [pair][i], 17.2 KB
    __shared__ ull  Bs[33 * 65];
    __shared__ float sSa[64], sSb[64];

    const int t  = threadIdx.x;
    const int i0 = blockIdx.y * 64;
    const int j0 = blockIdx.x * 64;

    for (int idx = t; idx < 33 * 64; idx += 128) {
        int hh = idx >> 6, col = idx & 63;
        As[hh * 65 + col] = ((const ull*)g_AT)[hh * N_NODES + i0 + col];
        Bs[hh * 65 + col] = ((const ull*)g_BT)[hh * N_NODES + j0 + col];
    }
    if (t < 64)  sSa[t]      = g_Sa[i0 + t];
    else         sSb[t - 64] = g_Sb[j0 + t - 64];
    __syncthreads();

    const int tx = t & 7;       // j = j0 + tx + 8c
    const int ty = t >> 3;      // i = i0 + ty + 16r  (ty 0..15)

    const int PP = g_PP;
    const int NE = PP + g_NP;

    ull acc[4][8];
    #pragma unroll
    for (int r = 0; r < 4; r++)
        #pragma unroll
        for (int c = 0; c < 8; c++) acc[r][c] = 0ull;

    #pragma unroll 1
    for (int hh = 0; hh < PP; hh++)
        do_hh<0>(As + hh * 65, Bs + hh * 65, ty, tx, acc);
    #pragma unroll 1
    for (int hh = PP; hh < NE; hh++)
        do_hh<1>(As + hh * 65, Bs + hh * 65, ty, tx, acc);

    float Sar[4], Sbc[8];
    #pragma unroll
    for (int r = 0; r < 4; r++) Sar[r] = sSa[ty + 16 * r];
    #pragma unroll
    for (int c = 0; c < 8; c++) Sbc[c] = sSb[tx + 8 * c];

    const bool db = (i0 == j0);

    #pragma unroll
    for (int r = 0; r < 4; r++) {
        const int il = ty + 16 * r;
        float* prow = out + (size_t)(i0 + il) * N_NODES + j0 + tx;
        #pragma unroll
        for (int c = 0; c < 8; c++) {
            unsigned lo_u, hi_u;
            asm("mov.b64 {%0, %1}, %2;" : "=r"(lo_u), "=r"(hi_u) : "l"(acc[r][c]));
            float x = (__uint_as_float(lo_u) + __uint_as_float(hi_u)) + (Sar[r] + Sbc[c]);
            float e, T;
            asm("ex2.approx.f32 %0, %1;" : "=f"(e) : "f"(x * -1.4426950408889634f));
            asm("rcp.approx.f32 %0, %1;" : "=f"(T) : "f"(1.0f + e));
            if (db && il == tx + 8 * c) T = 0.0f;
            prow[8 * c] = T;
        }
    }
}

extern "C" void kernel_launch(void* const* d_in, const int* in_sizes, int n_in,
                              void* d_out, int out_size)
{
    const float* X     = (const float*)d_in[0];
    const float* W_enc = (const float*)d_in[1];
    const float* b_enc = (const float*)d_in[2];
    const float* W1    = (const float*)d_in[3];
    const float* b1    = (const float*)d_in[4];
    const float* W2    = (const float*)d_in[5];
    const float* b2    = (const float*)d_in[6];
    float* out = (float*)d_out;

    prep<<<128, 256>>>(X, W_enc, b_enc, W1, b1, W2, b2);
    dim3 grid(N_NODES / 64, N_NODES / 64);
    pairwise<<<grid, 128>>>(out);
}

// round 17
// speedup vs baseline: 1.0396x; 1.0396x over previous
#include <cuda_runtime.h>

typedef unsigned long long ull;

#define N_NODES 2048
#define NODE_DIM 128
#define HIDDEN 64

// Scratch (no allocation allowed — device globals; zero-initialized at load,
// pad slots are never written so they stay zero across all replays)
// Channel-permuted, pre-scaled staging: slots 0..P-1 = positive c (pad to even),
// then negatives (pad to even). Value scaled by |c_h|/2.
// Layout: float[(slot>>1)][node][slot&1] -> ull pairs [pair][node].
__device__ __align__(16) float g_AT[34 * N_NODES * 2];
__device__ __align__(16) float g_BT[34 * N_NODES * 2];
__device__ __align__(16) float g_Sa[N_NODES];            // b2 + sum_h (c/2) a_ih
__device__ __align__(16) float g_Sb[N_NODES];            // sum_h (c/2) b_jh
__device__ int g_PP;     // # positive pairs (ceil(P/2))
__device__ int g_NP;     // # negative pairs (ceil((64-P)/2))

// ---------------------------------------------------------------------------
// Fused prep: per block of 16 nodes:
//   phase A: H = X @ W_enc + b_enc           (into smem Hs)
//   phase B: [a|b] = H @ [Wa|Wb] (+b1 on a), scale each channel by |c_h|/2,
//            scatter-store into sign-permuted slots of g_AT/g_BT;
//            Sa/Sb separable sums via smem reduce.
// Slot permutation computed in-kernel via ballot masks (no setup kernel).
// ---------------------------------------------------------------------------
__global__ __launch_bounds__(256, 2) void prep(const float* __restrict__ X,
                                               const float* __restrict__ W_enc,
                                               const float* __restrict__ b_enc,
                                               const float* __restrict__ W1,
                                               const float* __restrict__ b1,
                                               const float* __restrict__ W2,
                                               const float* __restrict__ b2)
{
    __shared__ union {
        struct {
            float Xs[16][129];          // stride 129 -> conflict-free
            ull   We[NODE_DIM][32];     // W_enc col-pairs
        } A;
        ull W1s[128][32];               // phase B: full W1 as col-pairs
    } u;
    __shared__ float Hs[16][65];        // H tile, stride 65
    __shared__ ull   bes[32];           // b_enc pairs
    __shared__ ull   b1s[32];           // b1 pairs
    __shared__ float c2s[64];           // c/2 (signed)
    __shared__ float cab[64];           // |c|/2 per channel
    __shared__ int   sml[64];           // slot of h
    __shared__ unsigned smask[2];       // sign ballots (h 0..31, 32..63)
    __shared__ float pa[16][17], pb[16][17];

    const int t  = threadIdx.x;
    const int n0 = blockIdx.x * 16;
    const int tx = t & 15;              // node lane
    const int ty = t >> 4;              // 0..15

    // ---- phase A fills ----
    for (int idx = t; idx < NODE_DIM * 32; idx += 256) {
        int k = idx >> 5, p = idx & 31;
        u.A.We[k][p] = *(const ull*)&W_enc[k * HIDDEN + 2 * p];
    }
    for (int idx = t; idx < 16 * NODE_DIM; idx += 256) {
        int n = idx >> 7, d = idx & 127;
        u.A.Xs[n][d] = X[(n0 + n) * NODE_DIM + d];
    }
    if (t < 32) bes[t] = *(const ull*)&b_enc[2 * t];
    else if (t >= 64 && t < 96) b1s[t - 64] = *(const ull*)&b1[2 * (t - 64)];
    if (t >= 128 && t < 192) {
        int h = t - 128;
        float w = W2[h];
        c2s[h] = 0.5f * w;
        cab[h] = 0.5f * fabsf(w);
        unsigned m = __ballot_sync(0xffffffffu, w >= 0.0f);
        if ((t & 31) == 0) smask[(t >> 5) & 1] = m;
    }
    __syncthreads();

    // ---- slot permutation (between syncs; consumed after next sync) ----
    if (t >= 128 && t < 192) {
        int h = t - 128;
        unsigned mA = smask[0], mB = smask[1];
        int P  = __popc(mA) + __popc(mB);
        int PP = (P + 1) >> 1;
        unsigned lowmask = (1u << (h & 31)) - 1u;
        bool pos;
        int posBefore;
        if (h < 32) {
            pos = (mA >> h) & 1u;
            posBefore = __popc(mA & lowmask);
        } else {
            pos = (mB >> (h - 32)) & 1u;
            posBefore = __popc(mA) + __popc(mB & lowmask);
        }
        sml[h] = pos ? posBefore : 2 * PP + (h - posBefore);
        if (t == 128) {
            g_PP = PP;
            g_NP = (64 - P + 1) >> 1;
        }
    }

    // ---- phase A compute: thread (tx, p0=ty) does pairs p0, p0+16 ----
    {
        ull acc0 = 0ull, acc1 = 0ull;
        #pragma unroll 8
        for (int k = 0; k < NODE_DIM; k++) {
            unsigned xu = __float_as_uint(u.A.Xs[tx][k]);
            ull x2;
            asm("mov.b64 %0, {%1, %2};" : "=l"(x2) : "r"(xu), "r"(xu));
            ull w0 = u.A.We[k][ty];
            ull w1 = u.A.We[k][ty + 16];
            asm("fma.rn.f32x2 %0, %1, %2, %0;" : "+l"(acc0) : "l"(x2), "l"(w0));
            asm("fma.rn.f32x2 %0, %1, %2, %0;" : "+l"(acc1) : "l"(x2), "l"(w1));
        }
        #pragma unroll
        for (int v = 0; v < 2; v++) {
            const int p = ty + 16 * v;
            ull a = v ? acc1 : acc0;
            asm("add.rn.f32x2 %0, %0, %1;" : "+l"(a) : "l"(bes[p]));
            unsigned lo_u, hi_u;
            asm("mov.b64 {%0, %1}, %2;" : "=r"(lo_u), "=r"(hi_u) : "l"(a));
            Hs[tx][2 * p]     = __uint_as_float(lo_u);
            Hs[tx][2 * p + 1] = __uint_as_float(hi_u);
        }
    }
    __syncthreads();     // Hs + sml complete; phase A buffers now dead

    // ---- phase B fill: W1 over the union ----
    for (int idx = t; idx < 128 * 32; idx += 256) {
        int k = idx >> 5, p = idx & 31;
        u.W1s[k][p] = *(const ull*)&W1[k * HIDDEN + 2 * p];
    }
    __syncthreads();

    // ---- phase B compute: thread (tx, ty) does 4 pair-chains ----
    ull acc[4];
    #pragma unroll
    for (int v = 0; v < 4; v++) acc[v] = 0ull;

    #pragma unroll 8
    for (int k = 0; k < HIDDEN; k++) {
        unsigned xu = __float_as_uint(Hs[tx][k]);
        ull x2;
        asm("mov.b64 %0, {%1, %2};" : "=l"(x2) : "r"(xu), "r"(xu));
        ull wa0 = u.W1s[k][ty];
        ull wa1 = u.W1s[k][ty + 16];
        ull wb0 = u.W1s[64 + k][ty];
        ull wb1 = u.W1s[64 + k][ty + 16];
        asm("fma.rn.f32x2 %0, %1, %2, %0;" : "+l"(acc[0]) : "l"(x2), "l"(wa0));
        asm("fma.rn.f32x2 %0, %1, %2, %0;" : "+l"(acc[1]) : "l"(x2), "l"(wa1));
        asm("fma.rn.f32x2 %0, %1, %2, %0;" : "+l"(acc[2]) : "l"(x2), "l"(wb0));
        asm("fma.rn.f32x2 %0, %1, %2, %0;" : "+l"(acc[3]) : "l"(x2), "l"(wb1));
    }

    float pA = 0.f, pB = 0.f;
    const int node = n0 + tx;
    #pragma unroll
    for (int v = 0; v < 4; v++) {
        const int pl = (v & 1) ? ty + 16 : ty;       // pair index within half
        const int h0 = 2 * pl, h1 = 2 * pl + 1;      // original channels
        ull w = acc[v];
        if (v < 2)
            asm("add.rn.f32x2 %0, %0, %1;" : "+l"(w) : "l"(b1s[pl]));
        unsigned lo_u, hi_u;
        asm("mov.b64 {%0, %1}, %2;" : "=r"(lo_u), "=r"(hi_u) : "l"(w));
        float vx = __uint_as_float(lo_u), vy = __uint_as_float(hi_u);
        // separable sum uses signed c/2 with UNSCALED values
        float contrib = vx * c2s[h0] + vy * c2s[h1];
        if (v < 2) pA += contrib; else pB += contrib;
        // scatter-store pre-scaled by |c|/2 into sign-permuted slots
        float* dst = (v < 2) ? g_AT : g_BT;
        const int s0 = sml[h0], s1 = sml[h1];
        dst[((s0 >> 1) * N_NODES + node) * 2 + (s0 & 1)] = vx * cab[h0];
        dst[((s1 >> 1) * N_NODES + node) * 2 + (s1 & 1)] = vy * cab[h1];
    }
    pa[ty][tx] = pA;
    pb[ty][tx] = pB;
    __syncthreads();

    if (t < 16) {
        float s = __ldg(b2);
        #pragma unroll
        for (int q = 0; q < 16; q++) s += pa[q][t];
        g_Sa[n0 + t] = s;
    } else if (t < 32) {
        float s = 0.f;
        #pragma unroll
        for (int q = 0; q < 16; q++) s += pb[q][t - 16];
        g_Sb[n0 + t - 16] = s;
    }
}

// ---------------------------------------------------------------------------
// Pairwise inner step. MODE 0: both c>=0 (acc += |s|, and.b64 imm).
// MODE 1: both c<0 (acc += -|s|, or.b64 imm). Pad slots are zero -> no-ops.
// 4x8 micro-tile: 12 LDS.64 feed 32 pair-chains (crossbar 69% vs 89% at 4x4).
// ---------------------------------------------------------------------------
template<int MODE>
__device__ __forceinline__ void do_hh(const ull* __restrict__ Arow,
                                      const ull* __restrict__ Brow,
                                      int ty, int tx, ull (&acc)[4][8])
{
    ull av[4], bv[8];
    #pragma unroll
    for (int r = 0; r < 4; r++) av[r] = Arow[ty + 16 * r];
    #pragma unroll
    for (int c = 0; c < 8; c++) bv[c] = Brow[tx + 8 * c];
    #pragma unroll
    for (int r = 0; r < 4; r++) {
        #pragma unroll
        for (int c = 0; c < 8; c++) {
            if (MODE == 0) {
                asm("{\n\t.reg .b64 s;\n\t"
                    "add.rn.f32x2 s, %1, %2;\n\t"
                    "and.b64 s, s, 0x7FFFFFFF7FFFFFFF;\n\t"
                    "add.rn.f32x2 %0, %0, s;\n\t}"
                    : "+l"(acc[r][c]) : "l"(av[r]), "l"(bv[c]));
            } else {
                asm("{\n\t.reg .b64 s;\n\t"
                    "add.rn.f32x2 s, %1, %2;\n\t"
                    "or.b64 s, s, 0x8000000080000000;\n\t"
                    "add.rn.f32x2 %0, %0, s;\n\t}"
                    : "+l"(acc[r][c]) : "l"(av[r]), "l"(bv[c]));
            }
        }
    }
}

// ---------------------------------------------------------------------------
// Main: logit_ij = Sa_i + Sb_j + sum_pos |s'| - sum_neg |s'|, out=sigmoid, diag=0
// 64x64 tile, 128 threads, 4x8 micro-tile, smem [pair][node] stride 65.
// ---------------------------------------------------------------------------
__global__ __launch_bounds__(128, 4) void pairwise(float* __restrict__ out)
{
    __shared__ ull  As[33 * 65];     // [pair][i], 17.2 KB
    __shared__ ull  Bs[33 * 65];
    __shared__ float sSa[64], sSb[64];

    const int t  = threadIdx.x;
    const int i0 = blockIdx.y * 64;
    const int j0 = blockIdx.x * 64;

    for (int idx = t; idx < 33 * 64; idx += 128) {
        int hh = idx >> 6, col = idx & 63;
        As[hh * 65 + col] = ((const ull*)g_AT)[hh * N_NODES + i0 + col];
        Bs[hh * 65 + col] = ((const ull*)g_BT)[hh * N_NODES + j0 + col];
    }
    if (t < 64)  sSa[t]      = g_Sa[i0 + t];
    else         sSb[t - 64] = g_Sb[j0 + t - 64];
    __syncthreads();

    const int tx = t & 7;       // j = j0 + tx + 8c
    const int ty = t >> 3;      // i = i0 + ty + 16r  (ty 0..15)

    const int PP = g_PP;
    const int NE = PP + g_NP;

    ull acc[4][8];
    #pragma unroll
    for (int r = 0; r < 4; r++)
        #pragma unroll
        for (int c = 0; c < 8; c++) acc[r][c] = 0ull;

    #pragma unroll 1
    for (int hh = 0; hh < PP; hh++)
        do_hh<0>(As + hh * 65, Bs + hh * 65, ty, tx, acc);
    #pragma unroll 1
    for (int hh = PP; hh < NE; hh++)
        do_hh<1>(As + hh * 65, Bs + hh * 65, ty, tx, acc);

    float Sar[4], Sbc[8];
    #pragma unroll
    for (int r = 0; r < 4; r++) Sar[r] = sSa[ty + 16 * r];
    #pragma unroll
    for (int c = 0; c < 8; c++) Sbc[c] = sSb[tx + 8 * c];

    const bool db = (i0 == j0);

    #pragma unroll
    for (int r = 0; r < 4; r++) {
        const int il = ty + 16 * r;
        float* prow = out + (size_t)(i0 + il) * N_NODES + j0 + tx;
        #pragma unroll
        for (int c = 0; c < 8; c++) {
            unsigned lo_u, hi_u;
            asm("mov.b64 {%0, %1}, %2;" : "=r"(lo_u), "=r"(hi_u) : "l"(acc[r][c]));
            float x = (__uint_as_float(lo_u) + __uint_as_float(hi_u)) + (Sar[r] + Sbc[c]);
            float e, T;
            asm("ex2.approx.f32 %0, %1;" : "=f"(e) : "f"(x * -1.4426950408889634f));
            asm("rcp.approx.f32 %0, %1;" : "=f"(T) : "f"(1.0f + e));
            if (db && il == tx + 8 * c) T = 0.0f;
            prow[8 * c] = T;
        }
    }
}

extern "C" void kernel_launch(void* const* d_in, const int* in_sizes, int n_in,
                              void* d_out, int out_size)
{
    const float* X     = (const float*)d_in[0];
    const float* W_enc = (const float*)d_in[1];
    const float* b_enc = (const float*)d_in[2];
    const float* W1    = (const float*)d_in[3];
    const float* b1    = (const float*)d_in[4];
    const float* W2    = (const float*)d_in[5];
    const float* b2    = (const float*)d_in[6];
    float* out = (float*)d_out;

    prep<<<128, 256>>>(X, W_enc, b_enc, W1, b1, W2, b2);
    dim3 grid(N_NODES / 64, N_NODES / 64);
    pairwise<<<grid, 128>>>(out);
}